// round 2
// baseline (speedup 1.0000x reference)
#include <cuda_runtime.h>
#include <math.h>
#include <stdint.h>

#define NN 100000
#define EE 1600000
#define FIN 128
#define HID 64
#define FOUT 40

// ---------------- scratch (device globals; no allocation allowed) ----------
__device__ int   g_deg[NN];
__device__ float g_dinv[NN];
__device__ float g_h1[(size_t)NN * HID];    // x @ W1
__device__ float g_agg1[(size_t)NN * HID];  // aggregated layer-1 (pre bias/relu)
__device__ float g_h2[(size_t)NN * FOUT];   // relu(agg1+b1) @ W2

// ---------------- degree / norm ----------------
__global__ void k_zero_deg() {
    int i = blockIdx.x * blockDim.x + threadIdx.x;
    if (i < NN) g_deg[i] = 0;
}

__global__ void k_count(const int* __restrict__ col) {
    int e = blockIdx.x * blockDim.x + threadIdx.x;
    if (e < EE) atomicAdd(&g_deg[col[e]], 1);
}

__global__ void k_dinv() {
    int i = blockIdx.x * blockDim.x + threadIdx.x;
    if (i < NN) g_dinv[i] = rsqrtf((float)(g_deg[i] + 1));  // +1 = self loop
}

// ---------------- GEMM1: h1 = x @ W1 ; agg1 = h1 * dinv^2 (self loop) ------
// block: 256 threads computes 32 rows x 64 cols. smem: x tile 16KB + W 32KB.
__global__ void k_gemm1(const float* __restrict__ x, const float* __restrict__ W) {
    __shared__ float xs[32 * FIN];    // [r][k], row-major, 16KB
    __shared__ float Ws[FIN * HID];   // [k][n], 32KB
    int t = threadIdx.x;
    int row0 = blockIdx.x * 32;

    // load W1 (128x64 = 2048 float4)
    const float4* W4 = (const float4*)W;
    float4* Ws4 = (float4*)Ws;
#pragma unroll
    for (int i = 0; i < 8; i++) Ws4[t + i * 256] = W4[t + i * 256];

    // load x tile (32x128 = 1024 float4), coalesced
    const float4* x4 = (const float4*)x;
    float4* xs4 = (float4*)xs;
#pragma unroll
    for (int i = 0; i < 4; i++) {
        int f = t + i * 256;          // f4 index; 32 f4 per row
        int r = f >> 5;
        int kq = f & 31;
        float4 v = make_float4(0.f, 0.f, 0.f, 0.f);
        if (row0 + r < NN) v = x4[(size_t)(row0 + r) * 32 + kq];
        xs4[f] = v;
    }
    __syncthreads();

    int tx = t & 15;   // cols 4*tx .. 4*tx+3
    int ty = t >> 4;   // rows ty and ty+16
    float acc0[4] = {0.f, 0.f, 0.f, 0.f};
    float acc1[4] = {0.f, 0.f, 0.f, 0.f};
#pragma unroll 4
    for (int k = 0; k < FIN; k++) {
        float a0 = xs[ty * FIN + k];          // broadcast across tx lanes
        float a1 = xs[(ty + 16) * FIN + k];
        float4 b = *(const float4*)&Ws[k * HID + 4 * tx];
        acc0[0] += a0 * b.x; acc0[1] += a0 * b.y; acc0[2] += a0 * b.z; acc0[3] += a0 * b.w;
        acc1[0] += a1 * b.x; acc1[1] += a1 * b.y; acc1[2] += a1 * b.z; acc1[3] += a1 * b.w;
    }
#pragma unroll
    for (int rr = 0; rr < 2; rr++) {
        int r = row0 + ty + rr * 16;
        if (r >= NN) continue;
        float* acc = rr ? acc1 : acc0;
        float d = g_dinv[r];
        float d2 = d * d;
        float4 h = make_float4(acc[0], acc[1], acc[2], acc[3]);
        *(float4*)&g_h1[(size_t)r * HID + 4 * tx] = h;
        float4 ag = make_float4(h.x * d2, h.y * d2, h.z * d2, h.w * d2);
        *(float4*)&g_agg1[(size_t)r * HID + 4 * tx] = ag;
    }
}

// ---------------- scatter layer 1: agg1[col] += h1[row] * dinv[row]*dinv[col]
__global__ void k_scatter1(const int* __restrict__ rows, const int* __restrict__ cols) {
    int tt = blockIdx.x * blockDim.x + threadIdx.x;
    if (tt >= EE * 16) return;
    int e = tt >> 4;
    int c = tt & 15;
    int r = __ldg(&rows[e]);
    int cl = __ldg(&cols[e]);
    float w = __ldg(&g_dinv[r]) * __ldg(&g_dinv[cl]);
    float4 v = *(const float4*)&g_h1[(size_t)r * HID + c * 4];
    float* dst = &g_agg1[(size_t)cl * HID + c * 4];
    asm volatile("red.global.add.v4.f32 [%0], {%1, %2, %3, %4};"
                 :: "l"(dst), "f"(v.x * w), "f"(v.y * w), "f"(v.z * w), "f"(v.w * w)
                 : "memory");
}

// ---------------- GEMM2: h2 = relu(agg1 + b1) @ W2 ; out = h2 * dinv^2 -----
// block: 256 threads computes 64 rows x 40 cols. xs padded to 68 floats/row.
__global__ void k_gemm2(const float* __restrict__ W2, const float* __restrict__ b1,
                        float* __restrict__ out) {
    __shared__ float xs[64 * 68];       // [r][k] pad 68 -> conflict-free a-reads
    __shared__ float Ws[HID * FOUT];    // [k][n] 64x40
    int t = threadIdx.x;
    int row0 = blockIdx.x * 64;

    for (int i = t; i < HID * FOUT; i += 256) Ws[i] = W2[i];

#pragma unroll
    for (int i = 0; i < 4; i++) {
        int f = t + i * 256;   // f4 index; 16 f4 per row
        int r = f >> 4;
        int kq = f & 15;
        float4 v = make_float4(0.f, 0.f, 0.f, 0.f);
        if (row0 + r < NN) {
            v = *(const float4*)&g_agg1[(size_t)(row0 + r) * HID + kq * 4];
            float4 bb = *(const float4*)&b1[kq * 4];
            v.x = fmaxf(v.x + bb.x, 0.f);
            v.y = fmaxf(v.y + bb.y, 0.f);
            v.z = fmaxf(v.z + bb.z, 0.f);
            v.w = fmaxf(v.w + bb.w, 0.f);
        }
        *(float4*)&xs[r * 68 + kq * 4] = v;
    }
    __syncthreads();

    int row = t >> 2;          // 0..63
    int c0 = (t & 3) * 10;     // col group of 10
    float acc[10];
#pragma unroll
    for (int j = 0; j < 10; j++) acc[j] = 0.f;
#pragma unroll 4
    for (int k = 0; k < HID; k++) {
        float a = xs[row * 68 + k];
#pragma unroll
        for (int j = 0; j < 10; j++) acc[j] += a * Ws[k * FOUT + c0 + j];
    }
    int r = row0 + row;
    if (r < NN) {
        float d = g_dinv[r];
        float d2 = d * d;
#pragma unroll
        for (int j = 0; j < 10; j++) {
            g_h2[(size_t)r * FOUT + c0 + j] = acc[j];
            out[(size_t)r * FOUT + c0 + j] = acc[j] * d2;   // self-loop init
        }
    }
}

// ---------------- scatter layer 2: out[col] += h2[row] * norm --------------
__global__ void k_scatter2(const int* __restrict__ rows, const int* __restrict__ cols,
                           float* __restrict__ out) {
    int tt = blockIdx.x * blockDim.x + threadIdx.x;
    if (tt >= EE * 10) return;
    int e = tt / 10;
    int c = tt - e * 10;
    int r = __ldg(&rows[e]);
    int cl = __ldg(&cols[e]);
    float w = __ldg(&g_dinv[r]) * __ldg(&g_dinv[cl]);
    float4 v = *(const float4*)&g_h2[(size_t)r * FOUT + c * 4];
    float* dst = &out[(size_t)cl * FOUT + c * 4];
    asm volatile("red.global.add.v4.f32 [%0], {%1, %2, %3, %4};"
                 :: "l"(dst), "f"(v.x * w), "f"(v.y * w), "f"(v.z * w), "f"(v.w * w)
                 : "memory");
}

// ---------------- log_softmax over 40 cols (in-place, + b2) ----------------
__global__ void k_lsm(float* __restrict__ out, const float* __restrict__ b2) {
    int warp = (blockIdx.x * blockDim.x + threadIdx.x) >> 5;
    int lane = threadIdx.x & 31;
    if (warp >= NN) return;
    float* p = out + (size_t)warp * FOUT;
    float a = p[lane] + __ldg(&b2[lane]);
    float b = -INFINITY;
    if (lane < 8) b = p[32 + lane] + __ldg(&b2[32 + lane]);
    float m = fmaxf(a, b);
#pragma unroll
    for (int o = 16; o; o >>= 1) m = fmaxf(m, __shfl_xor_sync(0xffffffffu, m, o));
    float s = expf(a - m) + (lane < 8 ? expf(b - m) : 0.f);
#pragma unroll
    for (int o = 16; o; o >>= 1) s += __shfl_xor_sync(0xffffffffu, s, o);
    float lse = m + logf(s);
    p[lane] = a - lse;
    if (lane < 8) p[32 + lane] = b - lse;
}

// ---------------- launcher ----------------
extern "C" void kernel_launch(void* const* d_in, const int* in_sizes, int n_in,
                              void* d_out, int out_size) {
    const float* x  = (const float*)d_in[0];
    const int*   ei = (const int*)d_in[1];     // [2][E]: rows then cols
    const float* W1 = (const float*)d_in[2];
    const float* b1 = (const float*)d_in[3];
    const float* W2 = (const float*)d_in[4];
    const float* b2 = (const float*)d_in[5];
    float* out = (float*)d_out;
    const int* rows = ei;
    const int* cols = ei + EE;

    k_zero_deg<<<(NN + 255) / 256, 256>>>();
    k_count<<<(EE + 255) / 256, 256>>>(cols);
    k_dinv<<<(NN + 255) / 256, 256>>>();

    k_gemm1<<<(NN + 31) / 32, 256>>>(x, W1);
    k_scatter1<<<(EE * 16 + 255) / 256, 256>>>(rows, cols);

    k_gemm2<<<(NN + 63) / 64, 256>>>(W2, b1, out);
    k_scatter2<<<(EE * 10 + 255) / 256, 256>>>(rows, cols, out);

    k_lsm<<<(NN * 32 + 255) / 256, 256>>>(out, b2);
}